// round 14
// baseline (speedup 1.0000x reference)
#include <cuda_runtime.h>
#include <cuda_fp16.h>
#include <cstdint>

// Problem constants
#define OUT_F 4096
#define IN_F  4096
#define MROWS 8192
#define NPACK (OUT_F * IN_F / 2)

// GEMM tiling: CTA 128x128, 8 warps (2 M x 4 N), warp tile 64x32, KT=128
#define MT 128
#define NT 128
#define KT 128
#define NKT (IN_F / KT)              // 32 k-tiles
#define STAGES 3
#define HALF_BYTES (MT * 128)        // 16384
#define A_BYTES (2 * HALF_BYTES)     // 32768 per stage
#define SMEM_DYN (STAGES * A_BYTES)  // 98304

// (n8, k16) B tiles
#define NTILES_N (OUT_F / 8)         // 512
#define NTILES_K (IN_F / 16)         // 256

// ---------------- scratch ------------------------------------------------------
__device__ uint2  g_wp[(size_t)NTILES_N * NTILES_K * 32];  // 32 MB: B fragment layout
__device__ __half g_x[(size_t)MROWS * IN_F];               // 64 MB: X as fp16
__device__ float  g_xsum[MROWS];

// ---------------- helpers ------------------------------------------------------
__device__ __forceinline__ uint32_t h2u(__half2 h) {
    __half2_raw r = *reinterpret_cast<__half2_raw*>(&h);
    return (uint32_t)r.x | ((uint32_t)r.y << 16);
}
__device__ __forceinline__ float2 u2f2(uint32_t u) {
    __half2_raw r;
    r.x = (unsigned short)(u & 0xFFFF);
    r.y = (unsigned short)(u >> 16);
    return __half22float2(*reinterpret_cast<__half2*>(&r));
}
__device__ __forceinline__ uint32_t s2u(const void* p) {
    uint32_t a;
    asm("{ .reg .u64 t; cvta.to.shared.u64 t, %1; cvt.u32.u64 %0, t; }" : "=r"(a) : "l"(p));
    return a;
}
__device__ __forceinline__ uint32_t swz(uint32_t off) { return off ^ ((off >> 3) & 0x70); }

__device__ __forceinline__ void cpa16(uint32_t dst, const void* src) {
    asm volatile("cp.async.cg.shared.global [%0], [%1], 16;" :: "r"(dst), "l"(src));
}
#define CP_COMMIT() asm volatile("cp.async.commit_group;" ::: "memory")
#define CP_WAIT1()  asm volatile("cp.async.wait_group 1;" ::: "memory")

__device__ __forceinline__ void ldm_x4(uint32_t* r, uint32_t addr) {
    asm volatile("ldmatrix.sync.aligned.m8n8.x4.shared.b16 {%0,%1,%2,%3}, [%4];"
                 : "=r"(r[0]), "=r"(r[1]), "=r"(r[2]), "=r"(r[3]) : "r"(addr));
}
// fp16-accumulator HMMA: D,C are 2 regs of f16x2
__device__ __forceinline__ void mma16816h(uint32_t* d, const uint32_t* a, const uint32_t* b) {
    asm volatile(
        "mma.sync.aligned.m16n8k16.row.col.f16.f16.f16.f16 "
        "{%0,%1}, {%2,%3,%4,%5}, {%6,%7}, {%0,%1};"
        : "+r"(d[0]), "+r"(d[1])
        : "r"(a[0]), "r"(a[1]), "r"(a[2]), "r"(a[3]), "r"(b[0]), "r"(b[1]));
}

// ---------------- merged prep (identical to R10) ---------------------------------
#define PREP_B_BLOCKS (NTILES_N * NTILES_K / 8)   // 16384
__global__ void prep(const float* __restrict__ x, const int* __restrict__ packed) {
    const int tid = threadIdx.x;
    if (blockIdx.x < MROWS) {
        const int row = blockIdx.x;
        const float4* xr = reinterpret_cast<const float4*>(x + (size_t)row * IN_F);
        uint2* dr = reinterpret_cast<uint2*>(g_x + (size_t)row * IN_F);
        float s = 0.f;
#pragma unroll
        for (int i = 0; i < 4; i++) {
            int j = i * 256 + tid;
            float4 v = xr[j];
            s += v.x + v.y + v.z + v.w;
            uint2 h;
            h.x = h2u(__floats2half2_rn(v.x, v.y));
            h.y = h2u(__floats2half2_rn(v.z, v.w));
            dr[j] = h;
        }
#pragma unroll
        for (int o = 16; o > 0; o >>= 1) s += __shfl_xor_sync(0xffffffffu, s, o);
        __shared__ float red[8];
        if ((tid & 31) == 0) red[tid >> 5] = s;
        __syncthreads();
        if (tid == 0) {
            float t = 0.f;
#pragma unroll
            for (int w = 0; w < 8; w++) t += red[w];
            g_xsum[row] = t;
        }
    } else {
        int tile = (blockIdx.x - MROWS) * 8 + (tid >> 5);
        int l = tid & 31;
        int tn = tile / NTILES_K;
        int tk = tile % NTILES_K;
        int n = tn * 8 + (l >> 2);
        int bi = n * (IN_F / 2) + tk * 8 + (l & 3);
        int b0 = packed[bi];
        int b1 = packed[bi + 4];
        uint2 o;
        o.x = h2u(__floats2half2_rn((float)((b0 << 28) >> 28), (float)((b0 << 24) >> 28)));
        o.y = h2u(__floats2half2_rn((float)((b1 << 28) >> 28), (float)((b1 << 24) >> 28)));
        g_wp[(size_t)tile * 32 + l] = o;
    }
}

// ------------------------------ main GEMM (fp16-acc probe) ------------------------
__global__ void __launch_bounds__(256, 1) gemm_q4(
    const float* __restrict__ scales, const float* __restrict__ zps,
    const float* __restrict__ bias, float* __restrict__ out)
{
    extern __shared__ char dyn_raw[];
    const uint32_t dynb = s2u(dyn_raw);

    const int tid = threadIdx.x;
    const int lane = tid & 31;
    const int wid = tid >> 5;
    const int warp_m = wid & 1;
    const int warp_n = wid >> 1;
    const int m_base = blockIdx.y * MT;
    const int n_base = blockIdx.x * NT;

    const int prow = tid >> 3;
    const int pcol = tid & 7;
    const char* a_src = reinterpret_cast<const char*>(
        g_x + ((size_t)(m_base + prow) * IN_F + pcol * 8));
    const uint32_t p_dst0 = swz((uint32_t)(prow * 128 + pcol * 16));

    auto produce = [&](int kt) {
        uint32_t as = dynb + (kt % STAGES) * A_BYTES;
        size_t koff = (size_t)kt * (KT * 2);
#pragma unroll
        for (int h = 0; h < 2; h++)
#pragma unroll
            for (int i = 0; i < 4; i++)
                cpa16(as + h * HALF_BYTES + p_dst0 + i * 32 * 128,
                      a_src + koff + h * 128 + (size_t)i * 32 * IN_F * 2);
    };

    produce(0); CP_COMMIT();
    produce(1); CP_COMMIT();

    const uint2* bptr = g_wp + ((size_t)(blockIdx.x * (NT / 8) + warp_n * 4) * NTILES_K) * 32 + lane;

    float acc[4][4][4];          // fp32 master accumulators
    uint32_t hacc[4][4][2];      // fp16 segment accumulators (K=32 segments)
#pragma unroll
    for (int im = 0; im < 4; im++)
#pragma unroll
        for (int jn = 0; jn < 4; jn++) {
#pragma unroll
            for (int r = 0; r < 4; r++) acc[im][jn][r] = 0.f;
            hacc[im][jn][0] = 0u; hacc[im][jn][1] = 0u;
        }

    const int a_lrow = lane & 15;
    const int a_lsel = lane >> 4;

    uint2 rbf[2][4];
#pragma unroll
    for (int jp = 0; jp < 4; jp++) rbf[0][jp] = bptr[(size_t)jp * NTILES_K * 32];

    for (int kt = 0; kt < NKT; kt++) {
        CP_WAIT1();
        __syncthreads();
        if (kt + 2 < NKT) produce(kt + 2);
        CP_COMMIT();

        uint32_t as = dynb + (kt % STAGES) * A_BYTES;

#pragma unroll
        for (int ks = 0; ks < 8; ks++) {
            const int tk = kt * 8 + ks;
            const int cur = tk & 1, nxt = cur ^ 1;
            if (tk + 1 < NTILES_K) {
#pragma unroll
                for (int jp = 0; jp < 4; jp++)
                    rbf[nxt][jp] = bptr[((size_t)jp * NTILES_K + tk + 1) * 32];
            }
            uint32_t ra[4][4];
            const uint32_t ah = as + (ks >> 2) * HALF_BYTES;
            const int ksh = ks & 3;
#pragma unroll
            for (int im = 0; im < 4; im++) {
                int r0 = warp_m * 64 + im * 16;
                ldm_x4(ra[im], ah + swz((uint32_t)((r0 + a_lrow) * 128 + (2 * ksh + a_lsel) * 16)));
            }
#pragma unroll
            for (int im = 0; im < 4; im++)
#pragma unroll
                for (int jn = 0; jn < 4; jn++)
                    mma16816h(hacc[im][jn], ra[im],
                              reinterpret_cast<const uint32_t*>(&rbf[cur][jn]));

            // fold fp16 segment into fp32 master every 2 k16 steps (K=32)
            if (ks & 1) {
#pragma unroll
                for (int im = 0; im < 4; im++)
#pragma unroll
                    for (int jn = 0; jn < 4; jn++) {
                        float2 f0 = u2f2(hacc[im][jn][0]);
                        float2 f1 = u2f2(hacc[im][jn][1]);
                        acc[im][jn][0] += f0.x;
                        acc[im][jn][1] += f0.y;
                        acc[im][jn][2] += f1.x;
                        acc[im][jn][3] += f1.y;
                        hacc[im][jn][0] = 0u;
                        hacc[im][jn][1] = 0u;
                    }
            }
        }
    }

    // ---------------- epilogue: dequant + bias ------------------------------------
    const int gid = lane >> 2;
    const int tg  = lane & 3;
    const int g   = n_base >> 7;
    const float sg = scales[g], zg = zps[g];
    const float szg = sg * zg;

#pragma unroll
    for (int im = 0; im < 4; im++) {
        int m0 = m_base + warp_m * 64 + im * 16 + gid;
        float xs0 = g_xsum[m0];
        float xs1 = g_xsum[m0 + 8];
        float sub0 = szg * xs0, sub1 = szg * xs1;
#pragma unroll
        for (int jn = 0; jn < 4; jn++) {
            int n0 = n_base + warp_n * 32 + jn * 8 + tg * 2;
            float b0 = bias[n0], b1 = bias[n0 + 1];

            float2 v0, v1;
            v0.x = sg * acc[im][jn][0] - sub0 + b0;
            v0.y = sg * acc[im][jn][1] - sub0 + b1;
            v1.x = sg * acc[im][jn][2] - sub1 + b0;
            v1.y = sg * acc[im][jn][3] - sub1 + b1;
            *reinterpret_cast<float2*>(out + (size_t)m0 * OUT_F + n0) = v0;
            *reinterpret_cast<float2*>(out + (size_t)(m0 + 8) * OUT_F + n0) = v1;
        }
    }
}

// ------------------------------- launch -------------------------------------------
extern "C" void kernel_launch(void* const* d_in, const int* in_sizes, int n_in,
                              void* d_out, int out_size) {
    const float* x      = (const float*)d_in[0];
    const int*   packed = (const int*)d_in[1];
    const float* scales = (const float*)d_in[2];
    const float* zps    = (const float*)d_in[3];
    const float* bias   = (const float*)d_in[4];
    float* out = (float*)d_out;

    prep<<<MROWS + PREP_B_BLOCKS, 256>>>(x, packed);

    cudaFuncSetAttribute(gemm_q4, cudaFuncAttributeMaxDynamicSharedMemorySize, SMEM_DYN);
    dim3 grid(OUT_F / NT, MROWS / MT);   // (32, 64)
    gemm_q4<<<grid, 256, SMEM_DYN>>>(scales, zps, bias, out);
}

// round 15
// speedup vs baseline: 1.6845x; 1.6845x over previous
#include <cuda_runtime.h>
#include <cuda_fp16.h>
#include <cstdint>

// Problem constants
#define OUT_F 4096
#define IN_F  4096
#define MROWS 8192
#define NPACK (OUT_F * IN_F / 2)

// GEMM tiling: CTA 128x128, 8 warps (2 M x 4 N), warp tile 64x32, KT=128
#define MT 128
#define NT 128
#define KT 128
#define NKT (IN_F / KT)              // 32 k-tiles
#define STAGES 3                     // A-only buffers, 2 groups in flight
#define HALF_BYTES (MT * 128)        // 16384 (one 128B-wide half-tile)
#define A_BYTES (2 * HALF_BYTES)     // 32768 per stage (k 0-63 | k 64-127)
#define SMEM_DYN (STAGES * A_BYTES)  // 98304 per CTA -> 2 CTAs/SM

// (n8, k16) B tiles
#define NTILES_N (OUT_F / 8)         // 512
#define NTILES_K (IN_F / 16)         // 256

// ---------------- scratch ------------------------------------------------------
__device__ uint2  g_wp[(size_t)NTILES_N * NTILES_K * 32];  // 32 MB: B fragment layout
__device__ __half g_x[(size_t)MROWS * IN_F];               // 64 MB: X as fp16
__device__ float  g_xsum[MROWS];

// ---------------- helpers ------------------------------------------------------
__device__ __forceinline__ uint32_t h2u(__half2 h) {
    __half2_raw r = *reinterpret_cast<__half2_raw*>(&h);
    return (uint32_t)r.x | ((uint32_t)r.y << 16);
}
__device__ __forceinline__ uint32_t s2u(const void* p) {
    uint32_t a;
    asm("{ .reg .u64 t; cvta.to.shared.u64 t, %1; cvt.u32.u64 %0, t; }" : "=r"(a) : "l"(p));
    return a;
}
__device__ __forceinline__ uint32_t swz(uint32_t off) { return off ^ ((off >> 3) & 0x70); }

__device__ __forceinline__ void cpa16(uint32_t dst, const void* src) {
    asm volatile("cp.async.cg.shared.global [%0], [%1], 16;" :: "r"(dst), "l"(src));
}
#define CP_COMMIT() asm volatile("cp.async.commit_group;" ::: "memory")
#define CP_WAIT1()  asm volatile("cp.async.wait_group 1;" ::: "memory")

__device__ __forceinline__ void ldm_x4(uint32_t* r, uint32_t addr) {
    asm volatile("ldmatrix.sync.aligned.m8n8.x4.shared.b16 {%0,%1,%2,%3}, [%4];"
                 : "=r"(r[0]), "=r"(r[1]), "=r"(r[2]), "=r"(r[3]) : "r"(addr));
}
__device__ __forceinline__ void mma16816(float* d, const uint32_t* a, const uint32_t* b) {
    asm volatile(
        "mma.sync.aligned.m16n8k16.row.col.f32.f16.f16.f32 "
        "{%0,%1,%2,%3}, {%4,%5,%6,%7}, {%8,%9}, {%0,%1,%2,%3};"
        : "+f"(d[0]), "+f"(d[1]), "+f"(d[2]), "+f"(d[3])
        : "r"(a[0]), "r"(a[1]), "r"(a[2]), "r"(a[3]), "r"(b[0]), "r"(b[1]));
}

// ---------------- merged prep ---------------------------------------------------
#define PREP_B_BLOCKS (NTILES_N * NTILES_K / 8)   // 16384
__global__ void prep(const float* __restrict__ x, const int* __restrict__ packed) {
    const int tid = threadIdx.x;
    if (blockIdx.x < MROWS) {
        const int row = blockIdx.x;
        const float4* xr = reinterpret_cast<const float4*>(x + (size_t)row * IN_F);
        uint2* dr = reinterpret_cast<uint2*>(g_x + (size_t)row * IN_F);
        float s = 0.f;
#pragma unroll
        for (int i = 0; i < 4; i++) {
            int j = i * 256 + tid;
            float4 v = xr[j];
            s += v.x + v.y + v.z + v.w;
            uint2 h;
            h.x = h2u(__floats2half2_rn(v.x, v.y));
            h.y = h2u(__floats2half2_rn(v.z, v.w));
            dr[j] = h;
        }
#pragma unroll
        for (int o = 16; o > 0; o >>= 1) s += __shfl_xor_sync(0xffffffffu, s, o);
        __shared__ float red[8];
        if ((tid & 31) == 0) red[tid >> 5] = s;
        __syncthreads();
        if (tid == 0) {
            float t = 0.f;
#pragma unroll
            for (int w = 0; w < 8; w++) t += red[w];
            g_xsum[row] = t;
        }
    } else {
        // B permute: warp per (n8,k16) tile; lane l writes its mma-B fragment
        int tile = (blockIdx.x - MROWS) * 8 + (tid >> 5);
        int l = tid & 31;
        int tn = tile / NTILES_K;
        int tk = tile % NTILES_K;
        int n = tn * 8 + (l >> 2);
        int bi = n * (IN_F / 2) + tk * 8 + (l & 3);
        int b0 = packed[bi];
        int b1 = packed[bi + 4];
        uint2 o;
        o.x = h2u(__floats2half2_rn((float)((b0 << 28) >> 28), (float)((b0 << 24) >> 28)));
        o.y = h2u(__floats2half2_rn((float)((b1 << 28) >> 28), (float)((b1 << 24) >> 28)));
        g_wp[(size_t)tile * 32 + l] = o;
    }
}

// ------------------------------ main GEMM ---------------------------------------
__global__ void __launch_bounds__(256, 2) gemm_q4(
    const float* __restrict__ scales, const float* __restrict__ zps,
    const float* __restrict__ bias, float* __restrict__ out)
{
    extern __shared__ char dyn_raw[];
    const uint32_t dynb = s2u(dyn_raw);

    const int tid = threadIdx.x;
    const int lane = tid & 31;
    const int wid = tid >> 5;
    const int warp_m = wid & 1;      // 2 warps along M -> 64 rows
    const int warp_n = wid >> 1;     // 4 warps along N -> 32 cols
    const int m_base = blockIdx.y * MT;
    const int n_base = blockIdx.x * NT;

    // A producer: stage holds two 128B-wide half-tiles (k 0-63, k 64-127)
    const int prow = tid >> 3;       // 0..31
    const int pcol = tid & 7;
    const char* a_src = reinterpret_cast<const char*>(
        g_x + ((size_t)(m_base + prow) * IN_F + pcol * 8));
    const uint32_t p_dst0 = swz((uint32_t)(prow * 128 + pcol * 16));

    auto produce = [&](int kt) {
        uint32_t as = dynb + (kt % STAGES) * A_BYTES;
        size_t koff = (size_t)kt * (KT * 2);          // 256B along K per k-tile
#pragma unroll
        for (int h = 0; h < 2; h++)
#pragma unroll
            for (int i = 0; i < 4; i++)
                cpa16(as + h * HALF_BYTES + p_dst0 + i * 32 * 128,
                      a_src + koff + h * 128 + (size_t)i * 32 * IN_F * 2);
    };

    produce(0); CP_COMMIT();
    produce(1); CP_COMMIT();

    // B fragment pointer
    const uint2* bptr = g_wp + ((size_t)(blockIdx.x * (NT / 8) + warp_n * 4) * NTILES_K) * 32 + lane;

    float acc[4][4][4];
#pragma unroll
    for (int im = 0; im < 4; im++)
#pragma unroll
        for (int jn = 0; jn < 4; jn++)
#pragma unroll
            for (int r = 0; r < 4; r++) acc[im][jn][r] = 0.f;

    const int a_lrow = lane & 15;
    const int a_lsel = lane >> 4;

    // B double buffer across k16 steps (gmem loads, no barrier dependence)
    uint2 rbf[2][4];
#pragma unroll
    for (int jp = 0; jp < 4; jp++) rbf[0][jp] = bptr[(size_t)jp * NTILES_K * 32];

    for (int kt = 0; kt < NKT; kt++) {
        CP_WAIT1();
        __syncthreads();
        if (kt + 2 < NKT) produce(kt + 2);
        CP_COMMIT();

        uint32_t as = dynb + (kt % STAGES) * A_BYTES;

#pragma unroll
        for (int ks = 0; ks < 8; ks++) {              // 8x k16 per k-tile
            const int tk = kt * 8 + ks;
            const int cur = tk & 1, nxt = cur ^ 1;
            if (tk + 1 < NTILES_K) {
#pragma unroll
                for (int jp = 0; jp < 4; jp++)
                    rbf[nxt][jp] = bptr[((size_t)jp * NTILES_K + tk + 1) * 32];
            }
            uint32_t ra[4][4];
            const uint32_t ah = as + (ks >> 2) * HALF_BYTES;
            const int ksh = ks & 3;
#pragma unroll
            for (int im = 0; im < 4; im++) {
                int r0 = warp_m * 64 + im * 16;
                ldm_x4(ra[im], ah + swz((uint32_t)((r0 + a_lrow) * 128 + (2 * ksh + a_lsel) * 16)));
            }
#pragma unroll
            for (int im = 0; im < 4; im++)
#pragma unroll
                for (int jn = 0; jn < 4; jn++)
                    mma16816(acc[im][jn], ra[im],
                             reinterpret_cast<const uint32_t*>(&rbf[cur][jn]));
        }
    }

    // ---------------- epilogue: dequant + bias ------------------------------------
    const int gid = lane >> 2;
    const int tg  = lane & 3;
    const int g   = n_base >> 7;
    const float sg = scales[g], zg = zps[g];
    const float szg = sg * zg;

#pragma unroll
    for (int im = 0; im < 4; im++) {
        int m0 = m_base + warp_m * 64 + im * 16 + gid;
        float xs0 = g_xsum[m0];
        float xs1 = g_xsum[m0 + 8];
        float sub0 = szg * xs0, sub1 = szg * xs1;
#pragma unroll
        for (int jn = 0; jn < 4; jn++) {
            int n0 = n_base + warp_n * 32 + jn * 8 + tg * 2;
            float b0 = bias[n0], b1 = bias[n0 + 1];

            float2 v0, v1;
            v0.x = sg * acc[im][jn][0] - sub0 + b0;
            v0.y = sg * acc[im][jn][1] - sub0 + b1;
            v1.x = sg * acc[im][jn][2] - sub1 + b0;
            v1.y = sg * acc[im][jn][3] - sub1 + b1;
            *reinterpret_cast<float2*>(out + (size_t)m0 * OUT_F + n0) = v0;
            *reinterpret_cast<float2*>(out + (size_t)(m0 + 8) * OUT_F + n0) = v1;
        }
    }
}

// ------------------------------- launch -------------------------------------------
extern "C" void kernel_launch(void* const* d_in, const int* in_sizes, int n_in,
                              void* d_out, int out_size) {
    const float* x      = (const float*)d_in[0];
    const int*   packed = (const int*)d_in[1];
    const float* scales = (const float*)d_in[2];
    const float* zps    = (const float*)d_in[3];
    const float* bias   = (const float*)d_in[4];
    float* out = (float*)d_out;

    prep<<<MROWS + PREP_B_BLOCKS, 256>>>(x, packed);

    cudaFuncSetAttribute(gemm_q4, cudaFuncAttributeMaxDynamicSharedMemorySize, SMEM_DYN);
    dim3 grid(OUT_F / NT, MROWS / MT);   // (32, 64)
    gemm_q4<<<grid, 256, SMEM_DYN>>>(scales, zps, bias, out);
}